// round 3
// baseline (speedup 1.0000x reference)
#include <cuda_runtime.h>
#include <math.h>

// Problem constants
#define BB 4
#define TT 2048
#define CC 1024
#define HH 16
#define HD 64
#define NTOK (BB * TT)          // 8192
#define JD 25                   // joined dim; cols j with j%25==24 are masked

// Scratch (alloc-free rule: device globals)
__device__ float g_q[NTOK * CC];
__device__ float g_k[NTOK * CC];
__device__ float g_v[NTOK * CC];
__device__ float g_y[NTOK * CC];

// ---------------------------------------------------------------------------
// GEMM: out[m][n] = sum_k A[m][k] * W[n][k] + bias[n]
// BM=128, BN=64, BK=16, 256 threads, 8x4 micro-tile per thread.
// ---------------------------------------------------------------------------
#define GBM 128
#define GBN 64
#define GBK 16
#define APAD (GBM + 4)

__global__ __launch_bounds__(256) void gemm_bias_kernel(
    const float* __restrict__ A, const float* __restrict__ W,
    const float* __restrict__ bias, float* __restrict__ out,
    int M, int N, int K)
{
    __shared__ float As[GBK][APAD];   // transposed: As[k][m]
    __shared__ float Ws[GBK][GBN];    // transposed: Ws[k][n]

    int tid = threadIdx.x;
    int ty = tid >> 4;             // 0..15 -> rows 8*ty..8*ty+7
    int tx = tid & 15;             // 0..15 -> cols 4*tx..4*tx+3
    int bm = blockIdx.y * GBM;
    int bn = blockIdx.x * GBN;

    // load mapping
    int ar0 = tid >> 2;            // 0..63   (A rows: ar0 and ar0+64)
    int ac  = (tid & 3) << 2;      // 0,4,8,12
    int wr  = tid >> 2;            // 0..63
    int wc  = (tid & 3) << 2;

    float acc[8][4] = {};

    for (int k0 = 0; k0 < K; k0 += GBK) {
        float4 a4a = *(const float4*)&A[(size_t)(bm + ar0) * K + k0 + ac];
        float4 a4b = *(const float4*)&A[(size_t)(bm + ar0 + 64) * K + k0 + ac];
        float4 w4  = *(const float4*)&W[(size_t)(bn + wr) * K + k0 + wc];
        __syncthreads();
        As[ac + 0][ar0] = a4a.x; As[ac + 1][ar0] = a4a.y;
        As[ac + 2][ar0] = a4a.z; As[ac + 3][ar0] = a4a.w;
        As[ac + 0][ar0 + 64] = a4b.x; As[ac + 1][ar0 + 64] = a4b.y;
        As[ac + 2][ar0 + 64] = a4b.z; As[ac + 3][ar0 + 64] = a4b.w;
        Ws[wc + 0][wr] = w4.x; Ws[wc + 1][wr] = w4.y;
        Ws[wc + 2][wr] = w4.z; Ws[wc + 3][wr] = w4.w;
        __syncthreads();

        #pragma unroll
        for (int kk = 0; kk < GBK; kk++) {
            float4 av0 = *(const float4*)&As[kk][ty << 3];
            float4 av1 = *(const float4*)&As[kk][(ty << 3) + 4];
            float4 wv  = *(const float4*)&Ws[kk][tx << 2];
            float a[8] = {av0.x, av0.y, av0.z, av0.w, av1.x, av1.y, av1.z, av1.w};
            float w[4] = {wv.x, wv.y, wv.z, wv.w};
            #pragma unroll
            for (int i = 0; i < 8; i++)
                #pragma unroll
                for (int j = 0; j < 4; j++)
                    acc[i][j] += a[i] * w[j];
        }
    }

    int n0 = bn + (tx << 2);
    float4 b4 = *(const float4*)&bias[n0];
    float bb[4] = {b4.x, b4.y, b4.z, b4.w};
    #pragma unroll
    for (int i = 0; i < 8; i++) {
        int m = bm + (ty << 3) + i;
        float4 o;
        o.x = acc[i][0] + bb[0];
        o.y = acc[i][1] + bb[1];
        o.z = acc[i][2] + bb[2];
        o.w = acc[i][3] + bb[3];
        *(float4*)&out[(size_t)m * N + n0] = o;
    }
}

// ---------------------------------------------------------------------------
// Flash attention, fp32. One CTA per (q-tile=64 rows, head, batch).
// BR=BC=64, HD=64. 256 threads = 16x16, 4x4 S / O micro-tile per thread.
// Online softmax; causal tiles only; column mask j%25==24 folded in.
// ---------------------------------------------------------------------------
#define PAD 68
#define ATTN_SMEM (4 * 64 * PAD * 4 + 2 * 64 * 4)

__global__ __launch_bounds__(256) void attn_kernel(
    const float* __restrict__ q, const float* __restrict__ k,
    const float* __restrict__ v, float* __restrict__ y)
{
    extern __shared__ float sm[];
    float (*Qs)[PAD]  = (float(*)[PAD])(sm);
    float (*KsT)[PAD] = (float(*)[PAD])(sm + 64 * PAD);
    float (*Vs)[PAD]  = (float(*)[PAD])(sm + 2 * 64 * PAD);
    float (*Ps)[PAD]  = (float(*)[PAD])(sm + 3 * 64 * PAD);
    float* m_sm = sm + 4 * 64 * PAD;
    float* l_sm = m_sm + 64;

    const int qt = blockIdx.x;     // 0..31
    const int h  = blockIdx.y;     // 0..15
    const int b  = blockIdx.z;     // 0..3
    const int tid = threadIdx.x;
    const int ty = tid >> 4;       // 0..15  -> rows 4ty..4ty+3
    const int tx = tid & 15;       // 0..15  -> cols 4tx..4tx+3

    // Load Q tile (rows = q tokens, cols = head dim)
    const float* qb = q + ((size_t)(b * TT + qt * 64)) * CC + h * HD;
    for (int idx = tid; idx < 64 * 16; idx += 256) {
        int r = idx >> 4, c = (idx & 15) << 2;
        *(float4*)&Qs[r][c] = *(const float4*)&qb[(size_t)r * CC + c];
    }
    if (tid < 64) { m_sm[tid] = -1e30f; l_sm[tid] = 0.0f; }

    float o[4][4] = {};
    const int i0 = qt * 64 + (ty << 2);   // global q row base for this thread

    __syncthreads();

    for (int kt = 0; kt <= qt; kt++) {
        // ---- load K (transposed into KsT[d][key]) and V (row-major) ----
        const float* kb = k + ((size_t)(b * TT + kt * 64)) * CC + h * HD;
        const float* vb = v + ((size_t)(b * TT + kt * 64)) * CC + h * HD;
        for (int idx = tid; idx < 64 * 16; idx += 256) {
            int r = idx >> 4, c = (idx & 15) << 2;  // r = key, c = d
            float4 k4 = *(const float4*)&kb[(size_t)r * CC + c];
            KsT[c + 0][r] = k4.x; KsT[c + 1][r] = k4.y;
            KsT[c + 2][r] = k4.z; KsT[c + 3][r] = k4.w;
            *(float4*)&Vs[r][c] = *(const float4*)&vb[(size_t)r * CC + c];
        }
        __syncthreads();

        // ---- S = Q @ K^T (4x4 per thread) ----
        float s[4][4] = {};
        for (int kk = 0; kk < 64; kk += 4) {
            float4 qv[4], kv[4];
            #pragma unroll
            for (int r = 0; r < 4; r++) qv[r] = *(const float4*)&Qs[(ty << 2) + r][kk];
            #pragma unroll
            for (int t = 0; t < 4; t++) kv[t] = *(const float4*)&KsT[kk + t][tx << 2];
            #pragma unroll
            for (int r = 0; r < 4; r++) {
                float qa[4] = {qv[r].x, qv[r].y, qv[r].z, qv[r].w};
                #pragma unroll
                for (int t = 0; t < 4; t++) {
                    float ka[4] = {kv[t].x, kv[t].y, kv[t].z, kv[t].w};
                    #pragma unroll
                    for (int c = 0; c < 4; c++)
                        s[r][c] += qa[t] * ka[c];
                }
            }
        }

        // ---- mask + scale ----
        const int j0 = kt * 64 + (tx << 2);
        #pragma unroll
        for (int r = 0; r < 4; r++) {
            int i = i0 + r;
            #pragma unroll
            for (int c = 0; c < 4; c++) {
                int j = j0 + c;
                bool valid = (j <= i) && ((j % JD) != (JD - 1));
                s[r][c] = valid ? s[r][c] * 0.125f : -1e30f;
            }
        }

        // ---- online softmax (row groups = 16 lanes within a warp) ----
        float mt[4], lt[4], m_old[4], m_new[4], scale[4];
        #pragma unroll
        for (int r = 0; r < 4; r++) {
            float mx = fmaxf(fmaxf(s[r][0], s[r][1]), fmaxf(s[r][2], s[r][3]));
            #pragma unroll
            for (int off = 8; off >= 1; off >>= 1)
                mx = fmaxf(mx, __shfl_xor_sync(0xffffffffu, mx, off));
            mt[r] = mx;
        }
        #pragma unroll
        for (int r = 0; r < 4; r++) {
            m_old[r] = m_sm[(ty << 2) + r];
            m_new[r] = fmaxf(m_old[r], mt[r]);
            scale[r] = __expf(m_old[r] - m_new[r]);
        }
        #pragma unroll
        for (int r = 0; r < 4; r++) {
            float sum = 0.0f;
            #pragma unroll
            for (int c = 0; c < 4; c++) {
                float p = __expf(s[r][c] - m_new[r]);
                s[r][c] = p;
                sum += p;
            }
            #pragma unroll
            for (int off = 8; off >= 1; off >>= 1)
                sum += __shfl_xor_sync(0xffffffffu, sum, off);
            lt[r] = sum;
        }
        if (tx == 0) {
            #pragma unroll
            for (int r = 0; r < 4; r++) {
                int row = (ty << 2) + r;
                m_sm[row] = m_new[r];
                l_sm[row] = l_sm[row] * scale[r] + lt[r];
            }
        }
        // stage P
        #pragma unroll
        for (int r = 0; r < 4; r++) {
            float4 p4 = make_float4(s[r][0], s[r][1], s[r][2], s[r][3]);
            *(float4*)&Ps[(ty << 2) + r][tx << 2] = p4;
        }
        __syncthreads();

        // ---- O = O*scale + P @ V ----
        #pragma unroll
        for (int r = 0; r < 4; r++)
            #pragma unroll
            for (int c = 0; c < 4; c++)
                o[r][c] *= scale[r];

        for (int kk = 0; kk < 64; kk += 4) {
            float4 pv[4], vv[4];
            #pragma unroll
            for (int r = 0; r < 4; r++) pv[r] = *(const float4*)&Ps[(ty << 2) + r][kk];
            #pragma unroll
            for (int t = 0; t < 4; t++) vv[t] = *(const float4*)&Vs[kk + t][tx << 2];
            #pragma unroll
            for (int r = 0; r < 4; r++) {
                float pa[4] = {pv[r].x, pv[r].y, pv[r].z, pv[r].w};
                #pragma unroll
                for (int t = 0; t < 4; t++) {
                    float va[4] = {vv[t].x, vv[t].y, vv[t].z, vv[t].w};
                    #pragma unroll
                    for (int c = 0; c < 4; c++)
                        o[r][c] += pa[t] * va[c];
                }
            }
        }
        __syncthreads();   // protect K/V/P before next iteration overwrites
    }

    // ---- normalize + write y (merged head transpose: y[b][t][h*HD+d]) ----
    #pragma unroll
    for (int r = 0; r < 4; r++) {
        float inv = 1.0f / l_sm[(ty << 2) + r];
        int t = qt * 64 + (ty << 2) + r;
        float4 o4 = make_float4(o[r][0] * inv, o[r][1] * inv,
                                o[r][2] * inv, o[r][3] * inv);
        *(float4*)&y[((size_t)(b * TT + t)) * CC + h * HD + (tx << 2)] = o4;
    }
}

// ---------------------------------------------------------------------------
extern "C" void kernel_launch(void* const* d_in, const int* in_sizes, int n_in,
                              void* d_out, int out_size)
{
    const float* x  = (const float*)d_in[0];
    const float* Wq = (const float*)d_in[1];
    const float* bq = (const float*)d_in[2];
    const float* Wk = (const float*)d_in[3];
    const float* bk = (const float*)d_in[4];
    const float* Wv = (const float*)d_in[5];
    const float* bv = (const float*)d_in[6];
    const float* Wp = (const float*)d_in[7];
    const float* bp = (const float*)d_in[8];
    float* out = (float*)d_out;

    float *q, *k, *v, *y;
    cudaGetSymbolAddress((void**)&q, g_q);
    cudaGetSymbolAddress((void**)&k, g_k);
    cudaGetSymbolAddress((void**)&v, g_v);
    cudaGetSymbolAddress((void**)&y, g_y);

    cudaFuncSetAttribute(attn_kernel,
                         cudaFuncAttributeMaxDynamicSharedMemorySize, ATTN_SMEM);

    dim3 gblk(256);
    dim3 ggrid(CC / GBN, NTOK / GBM);   // (16, 64)

    gemm_bias_kernel<<<ggrid, gblk>>>(x, Wq, bq, q, NTOK, CC, CC);
    gemm_bias_kernel<<<ggrid, gblk>>>(x, Wk, bk, k, NTOK, CC, CC);
    gemm_bias_kernel<<<ggrid, gblk>>>(x, Wv, bv, v, NTOK, CC, CC);

    dim3 agrid(TT / 64, HH, BB);      // (32, 16, 4)
    attn_kernel<<<agrid, 256, ATTN_SMEM>>>(q, k, v, y);

    gemm_bias_kernel<<<ggrid, gblk>>>(y, Wp, bp, out, NTOK, CC, CC);
}

// round 8
// speedup vs baseline: 1.4552x; 1.4552x over previous
#include <cuda_runtime.h>
#include <cuda_bf16.h>
#include <cstdint>
#include <math.h>

// Problem constants
#define BB 4
#define TT 2048
#define CC 1024
#define HH 16
#define HD 64
#define NTOK (BB * TT)          // 8192
#define JD 25                   // masked cols: j%25==24

// ---------------------------------------------------------------------------
// Scratch (alloc-free rule: device globals)
// ---------------------------------------------------------------------------
__device__ __align__(256) float g_q[NTOK * CC];
__device__ __align__(256) float g_k[NTOK * CC];
__device__ __align__(256) float g_v[NTOK * CC];
__device__ __align__(256) float g_y[NTOK * CC];
__device__ __align__(256) __nv_bfloat16 g_xh[NTOK * CC];
__device__ __align__(256) __nv_bfloat16 g_xl[NTOK * CC];
__device__ __align__(256) __nv_bfloat16 g_yh[NTOK * CC];
__device__ __align__(256) __nv_bfloat16 g_yl[NTOK * CC];
__device__ __align__(256) __nv_bfloat16 g_wh[4][CC * CC];
__device__ __align__(256) __nv_bfloat16 g_wl[4][CC * CC];

// ---------------------------------------------------------------------------
// PTX helpers (all plain-sm_103-legal: Ampere/Hopper-era instructions)
// ---------------------------------------------------------------------------
__device__ __forceinline__ uint32_t smem_u32(const void* p) {
    uint32_t a;
    asm("{ .reg .u64 t; cvta.to.shared.u64 t, %1; cvt.u32.u64 %0, t; }"
        : "=r"(a) : "l"(p));
    return a;
}
__device__ __forceinline__ void cp16(uint32_t s, const void* g) {
    asm volatile("cp.async.cg.shared.global [%0], [%1], 16;"
                 :: "r"(s), "l"(g) : "memory");
}
#define CP_COMMIT() asm volatile("cp.async.commit_group;" ::: "memory")
#define CP_WAIT(n)  asm volatile("cp.async.wait_group %0;" :: "n"(n) : "memory")

__device__ __forceinline__ void ldsm4(uint32_t* r, uint32_t addr) {
    asm volatile("ldmatrix.sync.aligned.m8n8.x4.shared.b16 {%0,%1,%2,%3}, [%4];"
        : "=r"(r[0]), "=r"(r[1]), "=r"(r[2]), "=r"(r[3]) : "r"(addr));
}
__device__ __forceinline__ void mma_bf16(float* c, const uint32_t* a,
                                         uint32_t b0, uint32_t b1) {
    asm volatile(
        "mma.sync.aligned.m16n8k16.row.col.f32.bf16.bf16.f32 "
        "{%0,%1,%2,%3}, {%4,%5,%6,%7}, {%8,%9}, {%0,%1,%2,%3};"
        : "+f"(c[0]), "+f"(c[1]), "+f"(c[2]), "+f"(c[3])
        : "r"(a[0]), "r"(a[1]), "r"(a[2]), "r"(a[3]), "r"(b0), "r"(b1));
}

// ---------------------------------------------------------------------------
// Split fp32 -> bf16 hi/lo
// ---------------------------------------------------------------------------
__global__ __launch_bounds__(256) void cvt_split_kernel(
    const float* __restrict__ in, __nv_bfloat16* __restrict__ hi,
    __nv_bfloat16* __restrict__ lo, int n4)
{
    int i = blockIdx.x * 256 + threadIdx.x;
    if (i >= n4) return;
    float4 f = ((const float4*)in)[i];
    float fv[4] = {f.x, f.y, f.z, f.w};
    uint32_t hb[4], lb[4];
    #pragma unroll
    for (int j = 0; j < 4; j++) {
        __nv_bfloat16 h = __float2bfloat16_rn(fv[j]);
        __nv_bfloat16 l = __float2bfloat16_rn(fv[j] - __bfloat162float(h));
        hb[j] = (uint32_t)__bfloat16_as_ushort(h);
        lb[j] = (uint32_t)__bfloat16_as_ushort(l);
    }
    uint2 hu, lu;
    hu.x = hb[0] | (hb[1] << 16); hu.y = hb[2] | (hb[3] << 16);
    lu.x = lb[0] | (lb[1] << 16); lu.y = lb[2] | (lb[3] << 16);
    ((uint2*)hi)[i] = hu;
    ((uint2*)lo)[i] = lu;
}

// ---------------------------------------------------------------------------
// mma.sync bf16 GEMM with 3-term split compensation.
// out[m][n] = sum_k A[m][k]*W[n][k] + bias[n]
// A = Ah + Al (bf16 pair), W = Wh + Wl.  acc += Ah*Wh + Ah*Wl + Al*Wh (fp32 regs)
// BM=128, BN=64, BK=32. 256 threads = 8 warps (4 x-rows, 2 n-cols), 32x32/warp.
// SMEM rows padded to 40 bf16 (80 B): 16B-aligned for cp.async, ldmatrix
// conflict-free (80*r mod 128 distinct for r=0..7). Double-buffered cp.async.
// ---------------------------------------------------------------------------
#define GBM 128
#define GBN 64
#define GBK 32
#define ROWB 80                         // bytes per smem row (32 bf16 + 8 pad)
#define AH_B 0
#define AL_B (128 * ROWB)               // 10240
#define WH_B (2 * 128 * ROWB)           // 20480
#define WL_B (WH_B + 64 * ROWB)         // 25600
#define BUFB (WL_B + 64 * ROWB)         // 30720
#define GEMM_SMEM (2 * BUFB)            // 61440
#define NIT (CC / GBK)                  // 32

__global__ __launch_bounds__(256) void mma_gemm_bias_kernel(
    const __nv_bfloat16* __restrict__ Ah, const __nv_bfloat16* __restrict__ Al,
    const __nv_bfloat16* __restrict__ Wh, const __nv_bfloat16* __restrict__ Wl,
    const float* __restrict__ bias, float* __restrict__ out)
{
    extern __shared__ char smem[];
    const uint32_t sb = smem_u32(smem);
    const int tid = threadIdx.x;
    const int wid = tid >> 5, lane = tid & 31;
    const int wm = (wid & 3) * 32;       // warp row base in tile
    const int wn = (wid >> 2) * 32;      // warp col base in tile
    const int bm = blockIdx.y * GBM;
    const int bn = blockIdx.x * GBN;

    // cp.async loader: one 16B segment id = (row, cseg)
    auto load_chunk = [&](int it, int b) {
        const int k0 = it * GBK;
        const uint32_t base = sb + b * BUFB;
        #pragma unroll
        for (int s = tid; s < 512; s += 256) {               // A hi+lo
            int row = s >> 2, cs = s & 3;
            size_t g = (size_t)(bm + row) * CC + k0 + cs * 8;
            uint32_t so = row * ROWB + cs * 16;
            cp16(base + AH_B + so, &Ah[g]);
            cp16(base + AL_B + so, &Al[g]);
        }
        {                                                     // W hi+lo (256 segs)
            int s = tid;
            int row = s >> 2, cs = s & 3;
            size_t g = (size_t)(bn + row) * CC + k0 + cs * 8;
            uint32_t so = row * ROWB + cs * 16;
            cp16(base + WH_B + so, &Wh[g]);
            cp16(base + WL_B + so, &Wl[g]);
        }
    };

    float acc[2][4][4] = {};   // [m-frag][n-frag][c-regs]

    load_chunk(0, 0);
    CP_COMMIT();

    const int lrow = lane & 15;          // ldmatrix row within 16
    const int lk   = (lane >> 4) * 16;   // ldmatrix k byte offset (0 or 16)

    for (int it = 0; it < NIT; it++) {
        if (it + 1 < NIT) { load_chunk(it + 1, (it + 1) & 1); CP_COMMIT(); CP_WAIT(1); }
        else              { CP_WAIT(0); }
        __syncthreads();

        const uint32_t base = sb + (it & 1) * BUFB;
        #pragma unroll
        for (int ks = 0; ks < 2; ks++) {
            const uint32_t koff = ks * 32 + lk;
            uint32_t ah[2][4], al[2][4], bh[2][4], bl[2][4];
            #pragma unroll
            for (int mi = 0; mi < 2; mi++) {
                uint32_t ra = base + (wm + mi * 16 + lrow) * ROWB + koff;
                ldsm4(ah[mi], ra + AH_B);
                ldsm4(al[mi], ra + AL_B);
            }
            #pragma unroll
            for (int nt = 0; nt < 2; nt++) {
                uint32_t rb = base + (wn + nt * 16 + lrow) * ROWB + koff;
                ldsm4(bh[nt], rb + WH_B);
                ldsm4(bl[nt], rb + WL_B);
            }
            // b frag for n-tile (nt,half): {raw[half], raw[half+2]}
            #pragma unroll
            for (int mi = 0; mi < 2; mi++)
                #pragma unroll
                for (int nt = 0; nt < 2; nt++)
                    #pragma unroll
                    for (int hf = 0; hf < 2; hf++) {
                        float* c = acc[mi][nt * 2 + hf];
                        mma_bf16(c, ah[mi], bh[nt][hf], bh[nt][hf + 2]);
                        mma_bf16(c, ah[mi], bl[nt][hf], bl[nt][hf + 2]);
                        mma_bf16(c, al[mi], bh[nt][hf], bh[nt][hf + 2]);
                    }
        }
        __syncthreads();
    }

    // epilogue: c frag -> gmem (+bias)
    const int cr = lane >> 2;            // 0..7
    const int cc2 = (lane & 3) * 2;      // 0,2,4,6
    #pragma unroll
    for (int mi = 0; mi < 2; mi++) {
        #pragma unroll
        for (int ni = 0; ni < 4; ni++) {
            int n = bn + wn + ni * 8 + cc2;
            float b0 = bias[n], b1 = bias[n + 1];
            int m0 = bm + wm + mi * 16 + cr;
            float2 v0 = make_float2(acc[mi][ni][0] + b0, acc[mi][ni][1] + b1);
            float2 v1 = make_float2(acc[mi][ni][2] + b0, acc[mi][ni][3] + b1);
            *(float2*)&out[(size_t)m0 * CC + n] = v0;
            *(float2*)&out[(size_t)(m0 + 8) * CC + n] = v1;
        }
    }
}

// ---------------------------------------------------------------------------
// Flash attention, fp32 SIMT (unchanged from passing R3 kernel)
// ---------------------------------------------------------------------------
#define PAD 68
#define ATTN_SMEM (4 * 64 * PAD * 4 + 2 * 64 * 4)

__global__ __launch_bounds__(256) void attn_kernel(
    const float* __restrict__ q, const float* __restrict__ k,
    const float* __restrict__ v, float* __restrict__ y)
{
    extern __shared__ float sm[];
    float (*Qs)[PAD]  = (float(*)[PAD])(sm);
    float (*KsT)[PAD] = (float(*)[PAD])(sm + 64 * PAD);
    float (*Vs)[PAD]  = (float(*)[PAD])(sm + 2 * 64 * PAD);
    float (*Ps)[PAD]  = (float(*)[PAD])(sm + 3 * 64 * PAD);
    float* m_sm = sm + 4 * 64 * PAD;
    float* l_sm = m_sm + 64;

    const int qt = blockIdx.x;
    const int h  = blockIdx.y;
    const int b  = blockIdx.z;
    const int tid = threadIdx.x;
    const int ty = tid >> 4;
    const int tx = tid & 15;

    const float* qb = q + ((size_t)(b * TT + qt * 64)) * CC + h * HD;
    for (int idx = tid; idx < 64 * 16; idx += 256) {
        int r = idx >> 4, c = (idx & 15) << 2;
        *(float4*)&Qs[r][c] = *(const float4*)&qb[(size_t)r * CC + c];
    }
    if (tid < 64) { m_sm[tid] = -1e30f; l_sm[tid] = 0.0f; }

    float o[4][4] = {};
    const int i0 = qt * 64 + (ty << 2);
    __syncthreads();

    for (int kt = 0; kt <= qt; kt++) {
        const float* kb = k + ((size_t)(b * TT + kt * 64)) * CC + h * HD;
        const float* vb = v + ((size_t)(b * TT + kt * 64)) * CC + h * HD;
        for (int idx = tid; idx < 64 * 16; idx += 256) {
            int r = idx >> 4, c = (idx & 15) << 2;
            float4 k4 = *(const float4*)&kb[(size_t)r * CC + c];
            KsT[c + 0][r] = k4.x; KsT[c + 1][r] = k4.y;
            KsT[c + 2][r] = k4.z; KsT[c + 3][r] = k4.w;
            *(float4*)&Vs[r][c] = *(const float4*)&vb[(size_t)r * CC + c];
        }
        __syncthreads();

        float s[4][4] = {};
        for (int kk = 0; kk < 64; kk += 4) {
            float4 qv[4], kv[4];
            #pragma unroll
            for (int r = 0; r < 4; r++) qv[r] = *(const float4*)&Qs[(ty << 2) + r][kk];
            #pragma unroll
            for (int t = 0; t < 4; t++) kv[t] = *(const float4*)&KsT[kk + t][tx << 2];
            #pragma unroll
            for (int r = 0; r < 4; r++) {
                float qa[4] = {qv[r].x, qv[r].y, qv[r].z, qv[r].w};
                #pragma unroll
                for (int t = 0; t < 4; t++) {
                    float ka[4] = {kv[t].x, kv[t].y, kv[t].z, kv[t].w};
                    #pragma unroll
                    for (int c = 0; c < 4; c++)
                        s[r][c] += qa[t] * ka[c];
                }
            }
        }

        const int j0 = kt * 64 + (tx << 2);
        #pragma unroll
        for (int r = 0; r < 4; r++) {
            int i = i0 + r;
            #pragma unroll
            for (int c = 0; c < 4; c++) {
                int j = j0 + c;
                bool valid = (j <= i) && ((j % JD) != (JD - 1));
                s[r][c] = valid ? s[r][c] * 0.125f : -1e30f;
            }
        }

        float mt[4], lt[4], m_old[4], m_new[4], scale[4];
        #pragma unroll
        for (int r = 0; r < 4; r++) {
            float mx = fmaxf(fmaxf(s[r][0], s[r][1]), fmaxf(s[r][2], s[r][3]));
            #pragma unroll
            for (int off = 8; off >= 1; off >>= 1)
                mx = fmaxf(mx, __shfl_xor_sync(0xffffffffu, mx, off));
            mt[r] = mx;
        }
        #pragma unroll
        for (int r = 0; r < 4; r++) {
            m_old[r] = m_sm[(ty << 2) + r];
            m_new[r] = fmaxf(m_old[r], mt[r]);
            scale[r] = __expf(m_old[r] - m_new[r]);
        }
        #pragma unroll
        for (int r = 0; r < 4; r++) {
            float sum = 0.0f;
            #pragma unroll
            for (int c = 0; c < 4; c++) {
                float p = __expf(s[r][c] - m_new[r]);
                s[r][c] = p;
                sum += p;
            }
            #pragma unroll
            for (int off = 8; off >= 1; off >>= 1)
                sum += __shfl_xor_sync(0xffffffffu, sum, off);
            lt[r] = sum;
        }
        if (tx == 0) {
            #pragma unroll
            for (int r = 0; r < 4; r++) {
                int row = (ty << 2) + r;
                m_sm[row] = m_new[r];
                l_sm[row] = l_sm[row] * scale[r] + lt[r];
            }
        }
        #pragma unroll
        for (int r = 0; r < 4; r++) {
            float4 p4 = make_float4(s[r][0], s[r][1], s[r][2], s[r][3]);
            *(float4*)&Ps[(ty << 2) + r][tx << 2] = p4;
        }
        __syncthreads();

        #pragma unroll
        for (int r = 0; r < 4; r++)
            #pragma unroll
            for (int c = 0; c < 4; c++)
                o[r][c] *= scale[r];

        for (int kk = 0; kk < 64; kk += 4) {
            float4 pv[4], vv[4];
            #pragma unroll
            for (int r = 0; r < 4; r++) pv[r] = *(const float4*)&Ps[(ty << 2) + r][kk];
            #pragma unroll
            for (int t = 0; t < 4; t++) vv[t] = *(const float4*)&Vs[kk + t][tx << 2];
            #pragma unroll
            for (int r = 0; r < 4; r++) {
                float pa[4] = {pv[r].x, pv[r].y, pv[r].z, pv[r].w};
                #pragma unroll
                for (int t = 0; t < 4; t++) {
                    float va[4] = {vv[t].x, vv[t].y, vv[t].z, vv[t].w};
                    #pragma unroll
                    for (int c = 0; c < 4; c++)
                        o[r][c] += pa[t] * va[c];
                }
            }
        }
        __syncthreads();
    }

    #pragma unroll
    for (int r = 0; r < 4; r++) {
        float inv = 1.0f / l_sm[(ty << 2) + r];
        int t = qt * 64 + (ty << 2) + r;
        float4 o4 = make_float4(o[r][0] * inv, o[r][1] * inv,
                                o[r][2] * inv, o[r][3] * inv);
        *(float4*)&y[((size_t)(b * TT + t)) * CC + h * HD + (tx << 2)] = o4;
    }
}

// ---------------------------------------------------------------------------
extern "C" void kernel_launch(void* const* d_in, const int* in_sizes, int n_in,
                              void* d_out, int out_size)
{
    const float* x  = (const float*)d_in[0];
    const float* Wq = (const float*)d_in[1];
    const float* bq = (const float*)d_in[2];
    const float* Wk = (const float*)d_in[3];
    const float* bk = (const float*)d_in[4];
    const float* Wv = (const float*)d_in[5];
    const float* bv = (const float*)d_in[6];
    const float* Wp = (const float*)d_in[7];
    const float* bp = (const float*)d_in[8];
    float* out = (float*)d_out;

    float *q, *k, *v, *y;
    __nv_bfloat16 *xh, *xl, *yh, *yl, *wh, *wl;
    cudaGetSymbolAddress((void**)&q,  g_q);
    cudaGetSymbolAddress((void**)&k,  g_k);
    cudaGetSymbolAddress((void**)&v,  g_v);
    cudaGetSymbolAddress((void**)&y,  g_y);
    cudaGetSymbolAddress((void**)&xh, g_xh);
    cudaGetSymbolAddress((void**)&xl, g_xl);
    cudaGetSymbolAddress((void**)&yh, g_yh);
    cudaGetSymbolAddress((void**)&yl, g_yl);
    cudaGetSymbolAddress((void**)&wh, g_wh);
    cudaGetSymbolAddress((void**)&wl, g_wl);

    cudaFuncSetAttribute(attn_kernel,
                         cudaFuncAttributeMaxDynamicSharedMemorySize, ATTN_SMEM);
    cudaFuncSetAttribute(mma_gemm_bias_kernel,
                         cudaFuncAttributeMaxDynamicSharedMemorySize, GEMM_SMEM);

    const int NX4 = NTOK * CC / 4;
    const int NW4 = CC * CC / 4;

    cvt_split_kernel<<<(NX4 + 255) / 256, 256>>>(x, xh, xl, NX4);
    cvt_split_kernel<<<(NW4 + 255) / 256, 256>>>(Wq, wh + 0 * (size_t)CC * CC,
                                                 wl + 0 * (size_t)CC * CC, NW4);
    cvt_split_kernel<<<(NW4 + 255) / 256, 256>>>(Wk, wh + 1 * (size_t)CC * CC,
                                                 wl + 1 * (size_t)CC * CC, NW4);
    cvt_split_kernel<<<(NW4 + 255) / 256, 256>>>(Wv, wh + 2 * (size_t)CC * CC,
                                                 wl + 2 * (size_t)CC * CC, NW4);
    cvt_split_kernel<<<(NW4 + 255) / 256, 256>>>(Wp, wh + 3 * (size_t)CC * CC,
                                                 wl + 3 * (size_t)CC * CC, NW4);

    dim3 ggrid(CC / GBN, NTOK / GBM);   // (16, 64)
    mma_gemm_bias_kernel<<<ggrid, 256, GEMM_SMEM>>>(
        xh, xl, wh + 0 * (size_t)CC * CC, wl + 0 * (size_t)CC * CC, bq, q);
    mma_gemm_bias_kernel<<<ggrid, 256, GEMM_SMEM>>>(
        xh, xl, wh + 1 * (size_t)CC * CC, wl + 1 * (size_t)CC * CC, bk, k);
    mma_gemm_bias_kernel<<<ggrid, 256, GEMM_SMEM>>>(
        xh, xl, wh + 2 * (size_t)CC * CC, wl + 2 * (size_t)CC * CC, bv, v);

    dim3 agrid(TT / 64, HH, BB);        // (32, 16, 4)
    attn_kernel<<<agrid, 256, ATTN_SMEM>>>(q, k, v, y);

    cvt_split_kernel<<<(NX4 + 255) / 256, 256>>>(y, yh, yl, NX4);
    mma_gemm_bias_kernel<<<ggrid, 256, GEMM_SMEM>>>(
        yh, yl, wh + 3 * (size_t)CC * CC, wl + 3 * (size_t)CC * CC, bp, out);
}

// round 12
// speedup vs baseline: 1.8170x; 1.2486x over previous
#include <cuda_runtime.h>
#include <cuda_bf16.h>
#include <cstdint>
#include <math.h>

// Problem constants
#define BB 4
#define TT 2048
#define CC 1024
#define HH 16
#define HD 64
#define NTOK (BB * TT)          // 8192
#define JD 25                   // masked cols: j%25==24

// ---------------------------------------------------------------------------
// Scratch (alloc-free rule: device globals)
// ---------------------------------------------------------------------------
__device__ __align__(256) float g_q[NTOK * CC];
__device__ __align__(256) float g_k[NTOK * CC];
__device__ __align__(256) float g_v[NTOK * CC];
__device__ __align__(256) float g_y[NTOK * CC];
__device__ __align__(256) __nv_bfloat16 g_xh[NTOK * CC];
__device__ __align__(256) __nv_bfloat16 g_xl[NTOK * CC];
__device__ __align__(256) __nv_bfloat16 g_yh[NTOK * CC];
__device__ __align__(256) __nv_bfloat16 g_yl[NTOK * CC];
__device__ __align__(256) __nv_bfloat16 g_wh[4][CC * CC];
__device__ __align__(256) __nv_bfloat16 g_wl[4][CC * CC];

// ---------------------------------------------------------------------------
// PTX helpers (plain-sm_103-legal)
// ---------------------------------------------------------------------------
__device__ __forceinline__ uint32_t smem_u32(const void* p) {
    uint32_t a;
    asm("{ .reg .u64 t; cvta.to.shared.u64 t, %1; cvt.u32.u64 %0, t; }"
        : "=r"(a) : "l"(p));
    return a;
}
__device__ __forceinline__ void cp16(uint32_t s, const void* g) {
    asm volatile("cp.async.cg.shared.global [%0], [%1], 16;"
                 :: "r"(s), "l"(g) : "memory");
}
#define CP_COMMIT() asm volatile("cp.async.commit_group;" ::: "memory")
#define CP_WAIT(n)  asm volatile("cp.async.wait_group %0;" :: "n"(n) : "memory")

__device__ __forceinline__ void ldsm4(uint32_t* r, uint32_t addr) {
    asm volatile("ldmatrix.sync.aligned.m8n8.x4.shared.b16 {%0,%1,%2,%3}, [%4];"
        : "=r"(r[0]), "=r"(r[1]), "=r"(r[2]), "=r"(r[3]) : "r"(addr));
}
__device__ __forceinline__ void mma_bf16(float* c, const uint32_t* a,
                                         uint32_t b0, uint32_t b1) {
    asm volatile(
        "mma.sync.aligned.m16n8k16.row.col.f32.bf16.bf16.f32 "
        "{%0,%1,%2,%3}, {%4,%5,%6,%7}, {%8,%9}, {%0,%1,%2,%3};"
        : "+f"(c[0]), "+f"(c[1]), "+f"(c[2]), "+f"(c[3])
        : "r"(a[0]), "r"(a[1]), "r"(a[2]), "r"(a[3]), "r"(b0), "r"(b1));
}
__device__ __forceinline__ uint32_t as_u32(__nv_bfloat162 h) {
    return *reinterpret_cast<uint32_t*>(&h);
}
// split packed pair: x -> hi bf16x2 + lo bf16x2
__device__ __forceinline__ void split2(float x0, float x1,
                                       uint32_t& hi, uint32_t& lo) {
    __nv_bfloat162 h = __float22bfloat162_rn(make_float2(x0, x1));
    float r0 = x0 - __bfloat162float(h.x);
    float r1 = x1 - __bfloat162float(h.y);
    __nv_bfloat162 l = __float22bfloat162_rn(make_float2(r0, r1));
    hi = as_u32(h); lo = as_u32(l);
}

// ---------------------------------------------------------------------------
// Split fp32 -> bf16 hi/lo (bulk)
// ---------------------------------------------------------------------------
__global__ __launch_bounds__(256) void cvt_split_kernel(
    const float* __restrict__ in, __nv_bfloat16* __restrict__ hi,
    __nv_bfloat16* __restrict__ lo, int n4)
{
    int i = blockIdx.x * 256 + threadIdx.x;
    if (i >= n4) return;
    float4 f = ((const float4*)in)[i];
    uint2 hu, lu;
    split2(f.x, f.y, hu.x, lu.x);
    split2(f.z, f.w, hu.y, lu.y);
    ((uint2*)hi)[i] = hu;
    ((uint2*)lo)[i] = lu;
}

// ---------------------------------------------------------------------------
// mma.sync bf16 GEMM with 3-term split compensation (unchanged from R8).
// ---------------------------------------------------------------------------
#define GBM 128
#define GBN 64
#define GBK 32
#define ROWB 80
#define AH_B 0
#define AL_B (128 * ROWB)
#define WH_B (2 * 128 * ROWB)
#define WL_B (WH_B + 64 * ROWB)
#define BUFB (WL_B + 64 * ROWB)
#define GEMM_SMEM (2 * BUFB)
#define NIT (CC / GBK)

__global__ __launch_bounds__(256) void mma_gemm_bias_kernel(
    const __nv_bfloat16* __restrict__ Ah, const __nv_bfloat16* __restrict__ Al,
    const __nv_bfloat16* __restrict__ Wh, const __nv_bfloat16* __restrict__ Wl,
    const float* __restrict__ bias, float* __restrict__ out)
{
    extern __shared__ char smem[];
    const uint32_t sb = smem_u32(smem);
    const int tid = threadIdx.x;
    const int wid = tid >> 5, lane = tid & 31;
    const int wm = (wid & 3) * 32;
    const int wn = (wid >> 2) * 32;
    const int bm = blockIdx.y * GBM;
    const int bn = blockIdx.x * GBN;

    auto load_chunk = [&](int it, int b) {
        const int k0 = it * GBK;
        const uint32_t base = sb + b * BUFB;
        #pragma unroll
        for (int s = tid; s < 512; s += 256) {
            int row = s >> 2, cs = s & 3;
            size_t g = (size_t)(bm + row) * CC + k0 + cs * 8;
            uint32_t so = row * ROWB + cs * 16;
            cp16(base + AH_B + so, &Ah[g]);
            cp16(base + AL_B + so, &Al[g]);
        }
        {
            int s = tid;
            int row = s >> 2, cs = s & 3;
            size_t g = (size_t)(bn + row) * CC + k0 + cs * 8;
            uint32_t so = row * ROWB + cs * 16;
            cp16(base + WH_B + so, &Wh[g]);
            cp16(base + WL_B + so, &Wl[g]);
        }
    };

    float acc[2][4][4] = {};

    load_chunk(0, 0);
    CP_COMMIT();

    const int lrow = lane & 15;
    const int lk   = (lane >> 4) * 16;

    for (int it = 0; it < NIT; it++) {
        if (it + 1 < NIT) { load_chunk(it + 1, (it + 1) & 1); CP_COMMIT(); CP_WAIT(1); }
        else              { CP_WAIT(0); }
        __syncthreads();

        const uint32_t base = sb + (it & 1) * BUFB;
        #pragma unroll
        for (int ks = 0; ks < 2; ks++) {
            const uint32_t koff = ks * 32 + lk;
            uint32_t ah[2][4], al[2][4], bh[2][4], bl[2][4];
            #pragma unroll
            for (int mi = 0; mi < 2; mi++) {
                uint32_t ra = base + (wm + mi * 16 + lrow) * ROWB + koff;
                ldsm4(ah[mi], ra + AH_B);
                ldsm4(al[mi], ra + AL_B);
            }
            #pragma unroll
            for (int nt = 0; nt < 2; nt++) {
                uint32_t rb = base + (wn + nt * 16 + lrow) * ROWB + koff;
                ldsm4(bh[nt], rb + WH_B);
                ldsm4(bl[nt], rb + WL_B);
            }
            #pragma unroll
            for (int mi = 0; mi < 2; mi++)
                #pragma unroll
                for (int nt = 0; nt < 2; nt++)
                    #pragma unroll
                    for (int hf = 0; hf < 2; hf++) {
                        float* c = acc[mi][nt * 2 + hf];
                        mma_bf16(c, ah[mi], bh[nt][hf], bh[nt][hf + 2]);
                        mma_bf16(c, ah[mi], bl[nt][hf], bl[nt][hf + 2]);
                        mma_bf16(c, al[mi], bh[nt][hf], bh[nt][hf + 2]);
                    }
        }
        __syncthreads();
    }

    const int cr = lane >> 2;
    const int cc2 = (lane & 3) * 2;
    #pragma unroll
    for (int mi = 0; mi < 2; mi++) {
        #pragma unroll
        for (int ni = 0; ni < 4; ni++) {
            int n = bn + wn + ni * 8 + cc2;
            float b0 = bias[n], b1 = bias[n + 1];
            int m0 = bm + wm + mi * 16 + cr;
            float2 v0 = make_float2(acc[mi][ni][0] + b0, acc[mi][ni][1] + b1);
            float2 v1 = make_float2(acc[mi][ni][2] + b0, acc[mi][ni][3] + b1);
            *(float2*)&out[(size_t)m0 * CC + n] = v0;
            *(float2*)&out[(size_t)(m0 + 8) * CC + n] = v1;
        }
    }
}

// ---------------------------------------------------------------------------
// Tensor-core flash attention, split-bf16 compensated.
// BR=128 q rows/CTA, BC=64 keys/iter, HD=64. 256 threads = 8 warps,
// warp w owns row stripe 16w..16w+15 (softmax warp-local).
// S = QhKh + QhKl + QlKh; P split in regs; O += PhVh + PhVl + PlVh.
// Row stride 144 B (128 data + 16 pad): ldmatrix conflict-free.
// ---------------------------------------------------------------------------
#define AROW 144
#define QH_OFF 0
#define QL_OFF (128 * AROW)             // 18432
#define KH_OFF (2 * 128 * AROW)         // 36864
#define KL_OFF (KH_OFF + 64 * AROW)     // 46080
#define VH_OFF (KL_OFF + 64 * AROW)     // 55296
#define VL_OFF (VH_OFF + 64 * AROW)     // 64512
#define ATTN_SMEM (VL_OFF + 64 * AROW)  // 73728

__global__ __launch_bounds__(256) void attn_mma_kernel(
    const float* __restrict__ q, const float* __restrict__ k,
    const float* __restrict__ v, float* __restrict__ y)
{
    extern __shared__ char smem[];
    const uint32_t sb = smem_u32(smem);
    const int qt = blockIdx.x;      // 0..15 (128-row q blocks)
    const int h  = blockIdx.y;
    const int b  = blockIdx.z;
    const int tid = threadIdx.x;
    const int wid = tid >> 5, lane = tid & 31;
    const int lrow = lane & 15;
    const int lk   = (lane >> 4) * 16;
    const int tg   = lane & 3;      // quad col
    const int qr   = lane >> 2;     // quad row

    // ---- stage Q (128x64 fp32 -> split bf16 hi/lo in smem) ----
    const float* qb = q + ((size_t)(b * TT + qt * 128)) * CC + h * HD;
    for (int idx = tid; idx < 2048; idx += 256) {
        int row = idx >> 4, c4 = (idx & 15) * 4;
        float4 f = *(const float4*)&qb[(size_t)row * CC + c4];
        uint2 hu, lu;
        split2(f.x, f.y, hu.x, lu.x);
        split2(f.z, f.w, hu.y, lu.y);
        uint32_t so = row * AROW + c4 * 2;
        *(uint2*)(smem + QH_OFF + so) = hu;
        *(uint2*)(smem + QL_OFF + so) = lu;
    }
    __syncthreads();

    // ---- Q fragments in registers (reused across all kt) ----
    uint32_t qh[4][4], ql[4][4];
    #pragma unroll
    for (int ks = 0; ks < 4; ks++) {
        uint32_t ra = sb + (wid * 16 + lrow) * AROW + ks * 32 + lk;
        ldsm4(qh[ks], ra + QH_OFF);
        ldsm4(ql[ks], ra + QL_OFF);
    }
    __syncthreads();

    float o[8][4] = {};
    float m0 = -1e30f, m1 = -1e30f, l0 = 0.0f, l1 = 0.0f;
    const int iband = qt * 128 + wid * 16;      // warp's min global row
    const int i0 = iband + qr, i1 = i0 + 8;     // this thread's rows

    const int ktmax = 2 * qt + 1;
    for (int kt = 0; kt <= ktmax; kt++) {
        // ---- load K tile [key][d] split, V tile transposed [d][key] split ----
        const float* kb = k + ((size_t)(b * TT + kt * 64)) * CC + h * HD;
        const float* vb = v + ((size_t)(b * TT + kt * 64)) * CC + h * HD;
        for (int idx = tid; idx < 1024; idx += 256) {
            int row = idx >> 4, c4 = (idx & 15) * 4;
            float4 f = *(const float4*)&kb[(size_t)row * CC + c4];
            uint2 hu, lu;
            split2(f.x, f.y, hu.x, lu.x);
            split2(f.z, f.w, hu.y, lu.y);
            uint32_t so = row * AROW + c4 * 2;
            *(uint2*)(smem + KH_OFF + so) = hu;
            *(uint2*)(smem + KL_OFF + so) = lu;

            float4 g = *(const float4*)&vb[(size_t)row * CC + c4];
            float vv[4] = {g.x, g.y, g.z, g.w};
            #pragma unroll
            for (int j = 0; j < 4; j++) {
                __nv_bfloat16 hh = __float2bfloat16_rn(vv[j]);
                __nv_bfloat16 ll = __float2bfloat16_rn(vv[j] - __bfloat162float(hh));
                uint32_t to = (c4 + j) * AROW + row * 2;
                *(__nv_bfloat16*)(smem + VH_OFF + to) = hh;
                *(__nv_bfloat16*)(smem + VL_OFF + to) = ll;
            }
        }
        __syncthreads();

        if (kt * 64 <= iband + 15) {    // warp has unmasked rows in this tile
            // ---- S = Q K^T ----
            float sc[8][4] = {};
            #pragma unroll
            for (int ks = 0; ks < 4; ks++) {
                #pragma unroll
                for (int nt = 0; nt < 4; nt++) {
                    uint32_t rb = sb + (nt * 16 + lrow) * AROW + ks * 32 + lk;
                    uint32_t bh[4], bl[4];
                    ldsm4(bh, rb + KH_OFF);
                    ldsm4(bl, rb + KL_OFF);
                    #pragma unroll
                    for (int hf = 0; hf < 2; hf++) {
                        float* c = sc[nt * 2 + hf];
                        mma_bf16(c, qh[ks], bh[hf], bh[hf + 2]);
                        mma_bf16(c, qh[ks], bl[hf], bl[hf + 2]);
                        mma_bf16(c, ql[ks], bh[hf], bh[hf + 2]);
                    }
                }
            }

            // ---- mask + scale ----
            const bool needC = (kt * 64 + 63) > iband;
            #pragma unroll
            for (int nf = 0; nf < 8; nf++) {
                int j0 = kt * 64 + nf * 8 + 2 * tg;
                int j1 = j0 + 1;
                bool ok0 = (j0 % JD) != (JD - 1);
                bool ok1 = (j1 % JD) != (JD - 1);
                bool v00 = ok0, v01 = ok1, v10 = ok0, v11 = ok1;
                if (needC) {
                    v00 = v00 && (j0 <= i0); v01 = v01 && (j1 <= i0);
                    v10 = v10 && (j0 <= i1); v11 = v11 && (j1 <= i1);
                }
                sc[nf][0] = v00 ? sc[nf][0] * 0.125f : -1e30f;
                sc[nf][1] = v01 ? sc[nf][1] * 0.125f : -1e30f;
                sc[nf][2] = v10 ? sc[nf][2] * 0.125f : -1e30f;
                sc[nf][3] = v11 ? sc[nf][3] * 0.125f : -1e30f;
            }

            // ---- online softmax (rows i0, i1) ----
            float mt0 = -1e30f, mt1 = -1e30f;
            #pragma unroll
            for (int nf = 0; nf < 8; nf++) {
                mt0 = fmaxf(mt0, fmaxf(sc[nf][0], sc[nf][1]));
                mt1 = fmaxf(mt1, fmaxf(sc[nf][2], sc[nf][3]));
            }
            #pragma unroll
            for (int off = 1; off <= 2; off <<= 1) {
                mt0 = fmaxf(mt0, __shfl_xor_sync(0xffffffffu, mt0, off));
                mt1 = fmaxf(mt1, __shfl_xor_sync(0xffffffffu, mt1, off));
            }
            float mn0 = fmaxf(m0, mt0), mn1 = fmaxf(m1, mt1);
            float es0 = __expf(m0 - mn0), es1 = __expf(m1 - mn1);
            m0 = mn0; m1 = mn1;

            float lt0 = 0.0f, lt1 = 0.0f;
            #pragma unroll
            for (int nf = 0; nf < 8; nf++) {
                sc[nf][0] = __expf(sc[nf][0] - mn0);
                sc[nf][1] = __expf(sc[nf][1] - mn0);
                sc[nf][2] = __expf(sc[nf][2] - mn1);
                sc[nf][3] = __expf(sc[nf][3] - mn1);
                lt0 += sc[nf][0] + sc[nf][1];
                lt1 += sc[nf][2] + sc[nf][3];
            }
            #pragma unroll
            for (int off = 1; off <= 2; off <<= 1) {
                lt0 += __shfl_xor_sync(0xffffffffu, lt0, off);
                lt1 += __shfl_xor_sync(0xffffffffu, lt1, off);
            }
            l0 = l0 * es0 + lt0;
            l1 = l1 * es1 + lt1;

            #pragma unroll
            for (int nf = 0; nf < 8; nf++) {
                o[nf][0] *= es0; o[nf][1] *= es0;
                o[nf][2] *= es1; o[nf][3] *= es1;
            }

            // ---- O += P V  (P frags from sc registers, split) ----
            #pragma unroll
            for (int ks = 0; ks < 4; ks++) {
                uint32_t ph[4], pl[4];
                split2(sc[2*ks][0],   sc[2*ks][1],   ph[0], pl[0]);
                split2(sc[2*ks][2],   sc[2*ks][3],   ph[1], pl[1]);
                split2(sc[2*ks+1][0], sc[2*ks+1][1], ph[2], pl[2]);
                split2(sc[2*ks+1][2], sc[2*ks+1][3], ph[3], pl[3]);
                #pragma unroll
                for (int nt = 0; nt < 4; nt++) {
                    uint32_t rb = sb + (nt * 16 + lrow) * AROW + ks * 32 + lk;
                    uint32_t bh[4], bl[4];
                    ldsm4(bh, rb + VH_OFF);
                    ldsm4(bl, rb + VL_OFF);
                    #pragma unroll
                    for (int hf = 0; hf < 2; hf++) {
                        float* c = o[nt * 2 + hf];
                        mma_bf16(c, ph, bh[hf], bh[hf + 2]);
                        mma_bf16(c, ph, bl[hf], bl[hf + 2]);
                        mma_bf16(c, pl, bh[hf], bh[hf + 2]);
                    }
                }
            }
        }
        __syncthreads();
    }

    // ---- epilogue: O / l -> y ----
    float inv0 = 1.0f / l0, inv1 = 1.0f / l1;
    #pragma unroll
    for (int nf = 0; nf < 8; nf++) {
        int col = h * HD + nf * 8 + 2 * tg;
        *(float2*)&y[((size_t)(b * TT + i0)) * CC + col] =
            make_float2(o[nf][0] * inv0, o[nf][1] * inv0);
        *(float2*)&y[((size_t)(b * TT + i1)) * CC + col] =
            make_float2(o[nf][2] * inv1, o[nf][3] * inv1);
    }
}

// ---------------------------------------------------------------------------
extern "C" void kernel_launch(void* const* d_in, const int* in_sizes, int n_in,
                              void* d_out, int out_size)
{
    const float* x  = (const float*)d_in[0];
    const float* Wq = (const float*)d_in[1];
    const float* bq = (const float*)d_in[2];
    const float* Wk = (const float*)d_in[3];
    const float* bk = (const float*)d_in[4];
    const float* Wv = (const float*)d_in[5];
    const float* bv = (const float*)d_in[6];
    const float* Wp = (const float*)d_in[7];
    const float* bp = (const float*)d_in[8];
    float* out = (float*)d_out;

    float *q, *k, *v, *y;
    __nv_bfloat16 *xh, *xl, *yh, *yl, *wh, *wl;
    cudaGetSymbolAddress((void**)&q,  g_q);
    cudaGetSymbolAddress((void**)&k,  g_k);
    cudaGetSymbolAddress((void**)&v,  g_v);
    cudaGetSymbolAddress((void**)&y,  g_y);
    cudaGetSymbolAddress((void**)&xh, g_xh);
    cudaGetSymbolAddress((void**)&xl, g_xl);
    cudaGetSymbolAddress((void**)&yh, g_yh);
    cudaGetSymbolAddress((void**)&yl, g_yl);
    cudaGetSymbolAddress((void**)&wh, g_wh);
    cudaGetSymbolAddress((void**)&wl, g_wl);

    cudaFuncSetAttribute(attn_mma_kernel,
                         cudaFuncAttributeMaxDynamicSharedMemorySize, ATTN_SMEM);
    cudaFuncSetAttribute(mma_gemm_bias_kernel,
                         cudaFuncAttributeMaxDynamicSharedMemorySize, GEMM_SMEM);

    const int NX4 = NTOK * CC / 4;
    const int NW4 = CC * CC / 4;

    cvt_split_kernel<<<(NX4 + 255) / 256, 256>>>(x, xh, xl, NX4);
    cvt_split_kernel<<<(NW4 + 255) / 256, 256>>>(Wq, wh + 0 * (size_t)CC * CC,
                                                 wl + 0 * (size_t)CC * CC, NW4);
    cvt_split_kernel<<<(NW4 + 255) / 256, 256>>>(Wk, wh + 1 * (size_t)CC * CC,
                                                 wl + 1 * (size_t)CC * CC, NW4);
    cvt_split_kernel<<<(NW4 + 255) / 256, 256>>>(Wv, wh + 2 * (size_t)CC * CC,
                                                 wl + 2 * (size_t)CC * CC, NW4);
    cvt_split_kernel<<<(NW4 + 255) / 256, 256>>>(Wp, wh + 3 * (size_t)CC * CC,
                                                 wl + 3 * (size_t)CC * CC, NW4);

    dim3 ggrid(CC / GBN, NTOK / GBM);   // (16, 64)
    mma_gemm_bias_kernel<<<ggrid, 256, GEMM_SMEM>>>(
        xh, xl, wh + 0 * (size_t)CC * CC, wl + 0 * (size_t)CC * CC, bq, q);
    mma_gemm_bias_kernel<<<ggrid, 256, GEMM_SMEM>>>(
        xh, xl, wh + 1 * (size_t)CC * CC, wl + 1 * (size_t)CC * CC, bk, k);
    mma_gemm_bias_kernel<<<ggrid, 256, GEMM_SMEM>>>(
        xh, xl, wh + 2 * (size_t)CC * CC, wl + 2 * (size_t)CC * CC, bv, v);

    dim3 agrid(TT / 128, HH, BB);       // (16, 16, 4)
    attn_mma_kernel<<<agrid, 256, ATTN_SMEM>>>(q, k, v, y);

    cvt_split_kernel<<<(NX4 + 255) / 256, 256>>>(y, yh, yl, NX4);
    mma_gemm_bias_kernel<<<ggrid, 256, GEMM_SMEM>>>(
        yh, yl, wh + 3 * (size_t)CC * CC, wl + 3 * (size_t)CC * CC, bp, out);
}